// round 3
// baseline (speedup 1.0000x reference)
#include <cuda_runtime.h>
#include <math.h>

#define VG  19
#define NN  608
#define LS  256
#define ROW 38912   /* 608*64 */
#define BCR 9728    /* 608*16 */
#define YPG 9961472 /* 256*608*64 */

__device__ float g_deg[NN];
__device__ float g_Nm[32 * 361];
__device__ float g_dt[LS * NN * 64];
__device__ float g_u [LS * NN * 64];
__device__ float g_z [LS * NN * 64];
__device__ float g_B [LS * NN * 16];
__device__ float g_C [LS * NN * 16];
__device__ float g_yp[4 * YPG];

__device__ __forceinline__ float softplusf(float x) {
    return x > 20.f ? x : log1pf(expf(x));
}

// ---------- GCN normalization ----------
__global__ void k_zero() {
    int i = blockIdx.x * blockDim.x + threadIdx.x;
    if (i < NN) g_deg[i] = 0.f;
    if (i < 32 * 361) g_Nm[i] = 0.f;
}
__global__ void k_deg(const int* __restrict__ ei, const float* __restrict__ ew, int E) {
    int i = blockIdx.x * blockDim.x + threadIdx.x;
    if (i < E)           atomicAdd(&g_deg[ei[E + i]], ew[i]);
    else if (i < E + NN) atomicAdd(&g_deg[i - E], 1.f);
}
__global__ void k_nmat(const int* __restrict__ ei, const float* __restrict__ ew, int E) {
    int i = blockIdx.x * blockDim.x + threadIdx.x;
    if (i < E) {
        int s = ei[i], d = ei[E + i];
        float nm = ew[i] * rsqrtf(fmaxf(g_deg[s], 1e-12f)) * rsqrtf(fmaxf(g_deg[d], 1e-12f));
        int bb = d / VG;
        g_Nm[bb * 361 + (d - bb * VG) * VG + (s - bb * VG)] = nm;
    } else if (i < E + NN) {
        int vv = i - E;
        float r = rsqrtf(fmaxf(g_deg[vv], 1e-12f));
        g_Nm[(vv / VG) * 361 + (vv % VG) * VG + (vv % VG)] = r * r;
    }
}

// ---------- pre: projections per (node, t) ----------
__global__ void __launch_bounds__(64) k_pre(
    const float* __restrict__ x_in, const float* __restrict__ ipw,
    const float* __restrict__ xpw,  const float* __restrict__ dtw,
    const float* __restrict__ dtb)
{
    __shared__ float xs[32], us[64], xd[34];
    int pos = blockIdx.x;           // node*256 + t
    int node = pos >> 8, t = pos & 255;
    int e = threadIdx.x;
    if (e < 32) xs[e] = x_in[pos * 32 + e];
    __syncthreads();
    float u = 0.f, z = 0.f;
    #pragma unroll
    for (int k = 0; k < 32; ++k) {
        float xk = xs[k];
        u = fmaf(xk, ipw[e * 32 + k], u);
        z = fmaf(xk, ipw[(64 + e) * 32 + k], z);
    }
    us[e] = u;
    int ob = t * ROW + node * 64 + e;
    g_u[ob] = u; g_z[ob] = z;
    __syncthreads();
    if (e < 34) {
        float a = 0.f;
        #pragma unroll
        for (int d = 0; d < 64; ++d) a = fmaf(xpw[e * 64 + d], us[d], a);
        xd[e] = a;
    }
    __syncthreads();
    g_dt[ob] = softplusf(fmaf(xd[0], dtw[e * 2], fmaf(xd[1], dtw[e * 2 + 1], dtb[e])));
    if (e < 32) {
        float val = xd[2 + e];
        int bc = t * BCR + node * 16 + (e & 15);
        if (e < 16) g_B[bc] = val; else g_C[bc] = val;
    }
}

// ---------- scan: persistent, 128 CTAs (batch x n-group) ----------
__global__ void __launch_bounds__(608, 1) k_scan(
    const float* __restrict__ A_log,
    const float* __restrict__ gAw, const float* __restrict__ gAb,
    const float* __restrict__ gBw, const float* __restrict__ gBb,
    const float* __restrict__ gCw, const float* __restrict__ gCb)
{
    extern __shared__ float sm[];
    float* WTA = sm;            // [d][e] 4096
    float* WTB = sm + 4096;
    float* WTC = sm + 8192;
    float* NM  = sm + 12288;    // 361
    float* S   = sm + 12652;    // 1216 float4
    float* Q   = sm + 17516;
    float* R   = sm + 22380;
    float* UA  = sm + 27244;    // 1216
    float* UB  = sm + 28460;
    float* QC  = sm + 29676;
    float* DTS = sm + 30892;
    float* US  = sm + 32108;
    float* BS  = sm + 33324;    // 80
    float* CS  = sm + 33404;    // 80
    float* bA  = sm + 33484; float* bB = sm + 33548; float* bC = sm + 33612;

    const int tid = threadIdx.x;
    const int b = blockIdx.x >> 2, g = blockIdx.x & 3;

    for (int i = tid; i < 4096; i += 608) {
        int d = i >> 6, e = i & 63;
        WTA[i] = gAw[e * 64 + d]; WTB[i] = gBw[e * 64 + d]; WTC[i] = gCw[e * 64 + d];
    }
    for (int i = tid; i < 361; i += 608) NM[i] = g_Nm[b * 361 + i];
    for (int i = tid; i < 4864; i += 608) S[i] = 0.f;
    if (tid < 64) { bA[tid] = gAb[tid]; bB[tid] = gBb[tid]; bC[tid] = gCb[tid]; }

    const int v = tid >> 5, a0 = tid & 31, a1 = (tid & 31) + 32;
    float4 AnA, AnB;
    AnA.x = -__expf(A_log[a0 * 16 + g * 4 + 0]);
    AnA.y = -__expf(A_log[a0 * 16 + g * 4 + 1]);
    AnA.z = -__expf(A_log[a0 * 16 + g * 4 + 2]);
    AnA.w = -__expf(A_log[a0 * 16 + g * 4 + 3]);
    AnB.x = -__expf(A_log[a1 * 16 + g * 4 + 0]);
    AnB.y = -__expf(A_log[a1 * 16 + g * 4 + 1]);
    AnB.z = -__expf(A_log[a1 * 16 + g * 4 + 2]);
    AnB.w = -__expf(A_log[a1 * 16 + g * 4 + 3]);

    float4* S4 = (float4*)S; float4* Q4 = (float4*)Q; float4* R4 = (float4*)R;
    float4* BS4 = (float4*)BS; float4* CS4 = (float4*)CS;
    float* yout = g_yp + g * YPG;
    __syncthreads();

    for (int t = 0; t < LS; ++t) {
        // 1. loads
        int base = t * ROW + b * 1216;
        DTS[tid] = g_dt[base + tid]; DTS[tid + 608] = g_dt[base + 608 + tid];
        US[tid]  = g_u[base + tid];  US[tid + 608]  = g_u[base + 608 + tid];
        if (tid < 76) {
            int vv = tid >> 2, n = tid & 3;
            int bc = t * BCR + (b * VG + vv) * 16 + g * 4 + n;
            BS[tid] = g_B[bc]; CS[tid] = g_C[bc];
        }
        __syncthreads();

        // 2. Q = Nm*S, UA = Nm*US
        {
            float4 qa = {0,0,0,0}, qb = {0,0,0,0}; float ua = 0.f, ub = 0.f;
            #pragma unroll
            for (int vp = 0; vp < VG; ++vp) {
                float nm = NM[v * VG + vp];
                float4 sa = S4[vp * 64 + a0], sb = S4[vp * 64 + a1];
                qa.x = fmaf(nm, sa.x, qa.x); qa.y = fmaf(nm, sa.y, qa.y);
                qa.z = fmaf(nm, sa.z, qa.z); qa.w = fmaf(nm, sa.w, qa.w);
                qb.x = fmaf(nm, sb.x, qb.x); qb.y = fmaf(nm, sb.y, qb.y);
                qb.z = fmaf(nm, sb.z, qb.z); qb.w = fmaf(nm, sb.w, qb.w);
                ua = fmaf(nm, US[vp * 64 + a0], ua);
                ub = fmaf(nm, US[vp * 64 + a1], ub);
            }
            Q4[v * 64 + a0] = qa; Q4[v * 64 + a1] = qb;
            UA[v * 64 + a0] = ua; UA[v * 64 + a1] = ub;
        }
        __syncthreads();

        // 3. R = WA @ Q, UB = WB @ UA + bB
        {
            float4 ra = {0,0,0,0}, rb = {0,0,0,0};
            float ua_ = bB[a0], ub_ = bB[a1];
            #pragma unroll 8
            for (int d = 0; d < 64; ++d) {
                float4 q = Q4[v * 64 + d];
                float uav = UA[v * 64 + d];
                float wa = WTA[d * 64 + a0], wb = WTA[d * 64 + a1];
                ra.x = fmaf(wa, q.x, ra.x); ra.y = fmaf(wa, q.y, ra.y);
                ra.z = fmaf(wa, q.z, ra.z); ra.w = fmaf(wa, q.w, ra.w);
                rb.x = fmaf(wb, q.x, rb.x); rb.y = fmaf(wb, q.y, rb.y);
                rb.z = fmaf(wb, q.z, rb.z); rb.w = fmaf(wb, q.w, rb.w);
                ua_ = fmaf(WTB[d * 64 + a0], uav, ua_);
                ub_ = fmaf(WTB[d * 64 + a1], uav, ub_);
            }
            R4[v * 64 + a0] = ra; R4[v * 64 + a1] = rb;
            UB[v * 64 + a0] = ua_; UB[v * 64 + a1] = ub_;
        }
        __syncthreads();

        // 4. E: S = (R + bA) * exp(dt*A) + UB*dt*B
        {
            float4 bsv = BS4[v];
            int i = v * 64 + a0;
            float dt = DTS[i], ub = UB[i] * dt, ba = bA[a0];
            float4 r = R4[i], s;
            s.x = fmaf(r.x + ba, __expf(dt * AnA.x), ub * bsv.x);
            s.y = fmaf(r.y + ba, __expf(dt * AnA.y), ub * bsv.y);
            s.z = fmaf(r.z + ba, __expf(dt * AnA.z), ub * bsv.z);
            s.w = fmaf(r.w + ba, __expf(dt * AnA.w), ub * bsv.w);
            S4[i] = s;
            i = v * 64 + a1;
            dt = DTS[i]; ub = UB[i] * dt; ba = bA[a1];
            r = R4[i];
            s.x = fmaf(r.x + ba, __expf(dt * AnB.x), ub * bsv.x);
            s.y = fmaf(r.y + ba, __expf(dt * AnB.y), ub * bsv.y);
            s.z = fmaf(r.z + ba, __expf(dt * AnB.z), ub * bsv.z);
            s.w = fmaf(r.w + ba, __expf(dt * AnB.w), ub * bsv.w);
            S4[i] = s;
        }
        __syncthreads();

        // 5. QC[v][d] = (Nm*S)[v][d][:] . C[v][:]
        {
            float4 qa = {0,0,0,0}, qb = {0,0,0,0};
            #pragma unroll
            for (int vp = 0; vp < VG; ++vp) {
                float nm = NM[v * VG + vp];
                float4 sa = S4[vp * 64 + a0], sb = S4[vp * 64 + a1];
                qa.x = fmaf(nm, sa.x, qa.x); qa.y = fmaf(nm, sa.y, qa.y);
                qa.z = fmaf(nm, sa.z, qa.z); qa.w = fmaf(nm, sa.w, qa.w);
                qb.x = fmaf(nm, sb.x, qb.x); qb.y = fmaf(nm, sb.y, qb.y);
                qb.z = fmaf(nm, sb.z, qb.z); qb.w = fmaf(nm, sb.w, qb.w);
            }
            float4 c = CS4[v];
            QC[v * 64 + a0] = qa.x * c.x + qa.y * c.y + qa.z * c.z + qa.w * c.w;
            QC[v * 64 + a1] = qb.x * c.x + qb.y * c.y + qb.z * c.z + qb.w * c.w;
        }
        __syncthreads();

        // 6. y_partial = WC @ QC + bC * sum(C)  -> global
        {
            float4 c = CS4[v];
            float cs = c.x + c.y + c.z + c.w;
            float ya = bC[a0] * cs, yb = bC[a1] * cs;
            #pragma unroll 8
            for (int d = 0; d < 64; ++d) {
                float qc = QC[v * 64 + d];
                ya = fmaf(WTC[d * 64 + a0], qc, ya);
                yb = fmaf(WTC[d * 64 + a1], qc, yb);
            }
            int ob = t * ROW + (b * VG + v) * 64;
            yout[ob + a0] = ya; yout[ob + a1] = yb;
        }
        __syncthreads();
    }
}

// ---------- post: y = (sum_g yp + D*u) * silu(z); out = y @ opw^T ----------
__global__ void __launch_bounds__(64) k_post(
    const float* __restrict__ Dp, const float* __restrict__ opw, float* __restrict__ out)
{
    __shared__ float ys[64];
    int pos = blockIdx.x;
    int node = pos >> 8, t = pos & 255;
    int e = threadIdx.x;
    int ib = t * ROW + node * 64 + e;
    float y = g_yp[ib] + g_yp[YPG + ib] + g_yp[2 * YPG + ib] + g_yp[3 * YPG + ib];
    y = fmaf(Dp[e], g_u[ib], y);
    float z = g_z[ib];
    y *= z / (1.f + expf(-z));
    ys[e] = y;
    __syncthreads();
    if (e < 32) {
        float a = 0.f;
        #pragma unroll
        for (int k = 0; k < 64; ++k) a = fmaf(opw[e * 64 + k], ys[k], a);
        out[pos * 32 + e] = a;
    }
}

extern "C" void kernel_launch(void* const* d_in, const int* in_sizes, int n_in,
                              void* d_out, int out_size) {
    const float* x_in = (const float*)d_in[0];
    const int*   ei   = (const int*)  d_in[1];
    const float* ew   = (const float*)d_in[2];
    const float* ipw  = (const float*)d_in[3];
    const float* xpw  = (const float*)d_in[4];
    const float* dtw  = (const float*)d_in[5];
    const float* dtb  = (const float*)d_in[6];
    const float* Alog = (const float*)d_in[7];
    const float* Dp   = (const float*)d_in[8];
    const float* opw  = (const float*)d_in[9];
    const float* gAw  = (const float*)d_in[10];
    const float* gAb  = (const float*)d_in[11];
    const float* gBw  = (const float*)d_in[12];
    const float* gBb  = (const float*)d_in[13];
    const float* gCw  = (const float*)d_in[14];
    const float* gCb  = (const float*)d_in[15];
    float* out = (float*)d_out;
    int E = in_sizes[1] / 2;

    static int smem_set = 0;
    if (!smem_set) {
        cudaFuncSetAttribute(k_scan, cudaFuncAttributeMaxDynamicSharedMemorySize, 33676 * 4);
        smem_set = 1;
    }

    k_zero<<<48, 256>>>();
    k_deg <<<(E + NN + 255) / 256, 256>>>(ei, ew, E);
    k_nmat<<<(E + NN + 255) / 256, 256>>>(ei, ew, E);
    k_pre <<<NN * LS, 64>>>(x_in, ipw, xpw, dtw, dtb);
    k_scan<<<128, 608, 33676 * 4>>>(Alog, gAw, gAb, gBw, gBb, gCw, gCb);
    k_post<<<NN * LS, 64>>>(Dp, opw, out);
}

// round 5
// speedup vs baseline: 1.1536x; 1.1536x over previous
#include <cuda_runtime.h>
#include <math.h>

#define VG  19
#define NN  608
#define LS  256
#define ROW 38912   /* 608*64 */
#define BCR 9728    /* 608*16 */
#define YPG 9961472 /* 256*608*64 */

__device__ __align__(16) float g_deg[NN];
__device__ __align__(16) float g_Nm[32 * 361];
__device__ __align__(16) float g_dt[LS * NN * 64];
__device__ __align__(16) float g_u [LS * NN * 64];
__device__ __align__(16) float g_z [LS * NN * 64];
__device__ __align__(16) float g_B [LS * NN * 16];
__device__ __align__(16) float g_C [LS * NN * 16];
__device__ __align__(16) float g_G [LS * NN * 64];
__device__ __align__(16) float g_WBT[4096];
__device__ __align__(16) float g_yp[4 * YPG];

__device__ __forceinline__ float softplusf(float x) {
    return x > 20.f ? x : log1pf(expf(x));
}

// ---------- GCN normalization ----------
__global__ void k_zero() {
    int i = blockIdx.x * blockDim.x + threadIdx.x;
    if (i < NN) g_deg[i] = 0.f;
    if (i < 32 * 361) g_Nm[i] = 0.f;
}
__global__ void k_deg(const int* __restrict__ ei, const float* __restrict__ ew, int E) {
    int i = blockIdx.x * blockDim.x + threadIdx.x;
    if (i < E)           atomicAdd(&g_deg[ei[E + i]], ew[i]);
    else if (i < E + NN) atomicAdd(&g_deg[i - E], 1.f);
}
__global__ void k_nmat(const int* __restrict__ ei, const float* __restrict__ ew, int E) {
    int i = blockIdx.x * blockDim.x + threadIdx.x;
    if (i < E) {
        int s = ei[i], d = ei[E + i];
        float nm = ew[i] * rsqrtf(fmaxf(g_deg[s], 1e-12f)) * rsqrtf(fmaxf(g_deg[d], 1e-12f));
        int bb = d / VG;
        g_Nm[bb * 361 + (d - bb * VG) * VG + (s - bb * VG)] = nm;
    } else if (i < E + NN) {
        int vv = i - E;
        float r = rsqrtf(fmaxf(g_deg[vv], 1e-12f));
        g_Nm[(vv / VG) * 361 + (vv % VG) * VG + (vv % VG)] = r * r;
    }
}
__global__ void k_tr(const float* __restrict__ gBw) {
    int i = blockIdx.x * blockDim.x + threadIdx.x;
    if (i < 4096) g_WBT[i] = gBw[(i & 63) * 64 + (i >> 6)];
}

// ---------- pre: projections per (node, t) ----------
__global__ void __launch_bounds__(64) k_pre(
    const float* __restrict__ x_in, const float* __restrict__ ipw,
    const float* __restrict__ xpw,  const float* __restrict__ dtw,
    const float* __restrict__ dtb)
{
    __shared__ float xs[32], us[64], xd[34];
    int pos = blockIdx.x;
    int node = pos >> 8, t = pos & 255;
    int e = threadIdx.x;
    if (e < 32) xs[e] = x_in[pos * 32 + e];
    __syncthreads();
    float u = 0.f, z = 0.f;
    #pragma unroll
    for (int k = 0; k < 32; ++k) {
        float xk = xs[k];
        u = fmaf(xk, ipw[e * 32 + k], u);
        z = fmaf(xk, ipw[(64 + e) * 32 + k], z);
    }
    us[e] = u;
    int ob = t * ROW + node * 64 + e;
    g_u[ob] = u; g_z[ob] = z;
    __syncthreads();
    if (e < 34) {
        float a = 0.f;
        #pragma unroll
        for (int d = 0; d < 64; ++d) a = fmaf(xpw[e * 64 + d], us[d], a);
        xd[e] = a;
    }
    __syncthreads();
    g_dt[ob] = softplusf(fmaf(xd[0], dtw[e * 2], fmaf(xd[1], dtw[e * 2 + 1], dtb[e])));
    if (e < 32) {
        float val = xd[2 + e];
        int bc = t * BCR + node * 16 + (e & 15);
        if (e < 16) g_B[bc] = val; else g_C[bc] = val;
    }
}

// ---------- ub precompute: G[t,v,e] = (gB@(Nm u) + bB) * dt ----------
__global__ void __launch_bounds__(320) k_ub(const float* __restrict__ gBb) {
    __shared__ __align__(16) float us[1216];
    __shared__ __align__(16) float ua[1216];
    __shared__ __align__(16) float wbt[4096];
    __shared__ __align__(16) float bb[64];
    __shared__ __align__(16) float nm[364];
    int tb = blockIdx.x, t = tb >> 5, b = tb & 31;
    int tid = threadIdx.x;
    float4* us4 = (float4*)us;
    const float4* gu4 = (const float4*)(g_u + t * ROW + b * 1216);
    if (tid < 304) us4[tid] = gu4[tid];
    for (int i = tid; i < 4096; i += 320) wbt[i] = g_WBT[i];
    for (int i = tid; i < 361; i += 320) nm[i] = g_Nm[b * 361 + i];
    if (tid < 64) bb[tid] = gBb[tid];
    __syncthreads();
    if (tid < 304) {
        int vi = tid >> 4, ei = tid & 15;
        float4 a = {0, 0, 0, 0};
        #pragma unroll
        for (int vp = 0; vp < VG; ++vp) {
            float n = nm[vi * VG + vp];
            float4 u = us4[vp * 16 + ei];
            a.x = fmaf(n, u.x, a.x); a.y = fmaf(n, u.y, a.y);
            a.z = fmaf(n, u.z, a.z); a.w = fmaf(n, u.w, a.w);
        }
        ((float4*)ua)[vi * 16 + ei] = a;
    }
    __syncthreads();
    if (tid < 304) {
        int vi = tid >> 4, ei = tid & 15;
        float4 acc = ((const float4*)bb)[ei];
        const float4* wbt4 = (const float4*)wbt;
        #pragma unroll 4
        for (int d = 0; d < 64; ++d) {
            float uav = ua[(vi << 6) + d];
            float4 w = wbt4[(d << 4) + ei];
            acc.x = fmaf(w.x, uav, acc.x); acc.y = fmaf(w.y, uav, acc.y);
            acc.z = fmaf(w.z, uav, acc.z); acc.w = fmaf(w.w, uav, acc.w);
        }
        int gb = t * ROW + (b * VG + vi) * 64 + (ei << 2);
        float4 dt4 = *(const float4*)&g_dt[gb];
        acc.x *= dt4.x; acc.y *= dt4.y; acc.z *= dt4.z; acc.w *= dt4.w;
        *(float4*)&g_G[gb] = acc;
    }
}

// ---------- scan: persistent, 128 CTAs ----------
#define O_WA  0
#define O_WC  4096
#define O_NM  8192
#define O_S   8560
#define O_Q   13424
#define O_RN  18288
#define O_QC  23152
#define O_BS  24368
#define O_CS  24448
#define O_CSV 24528
#define O_BA  24552
#define O_BC  24616
#define SMTOT 24680

__global__ void __launch_bounds__(608, 1) k_scan(
    const float* __restrict__ A_log,
    const float* __restrict__ gAw, const float* __restrict__ gAb,
    const float* __restrict__ gCw, const float* __restrict__ gCb)
{
    extern __shared__ __align__(16) float sm[];
    float* WAe = sm + O_WA;   float* WCe = sm + O_WC;
    float* NMs = sm + O_NM;   float* Rn  = sm + O_RN;
    float* QCs = sm + O_QC;   float* CSVs= sm + O_CSV;
    float* bAs = sm + O_BA;
    float4* S4  = (float4*)(sm + O_S);
    float4* Q4  = (float4*)(sm + O_Q);
    float4* Rn4 = (float4*)(sm + O_RN);
    float4* BS4 = (float4*)(sm + O_BS);
    float4* CS4 = (float4*)(sm + O_CS);
    const float4* WAe4 = (const float4*)WAe;
    const float4* WCe4 = (const float4*)WCe;
    const float4* bC4  = (const float4*)(sm + O_BC);

    const int tid = threadIdx.x;
    const int b = blockIdx.x >> 2, g = blockIdx.x & 3;

    for (int i = tid; i < 4096; i += 608) {
        WAe[i] = gAw[(i & 63) * 64 + (i >> 6)];
        WCe[i] = gCw[(i & 63) * 64 + (i >> 6)];
    }
    for (int i = tid; i < 361; i += 608) NMs[i] = g_Nm[b * 361 + i];
    for (int i = tid; i < 4864; i += 608) Rn[i] = 0.f;
    if (tid < 64) { bAs[tid] = gAb[tid]; sm[O_BC + tid] = gCb[tid]; }

    const int v = tid >> 5, e0 = tid & 31, e1 = e0 + 32;
    float Ae0x = -__expf(A_log[e0 * 16 + g * 4 + 0]);
    float Ae0y = -__expf(A_log[e0 * 16 + g * 4 + 1]);
    float Ae0z = -__expf(A_log[e0 * 16 + g * 4 + 2]);
    float Ae0w = -__expf(A_log[e0 * 16 + g * 4 + 3]);
    float Ae1x = -__expf(A_log[e1 * 16 + g * 4 + 0]);
    float Ae1y = -__expf(A_log[e1 * 16 + g * 4 + 1]);
    float Ae1z = -__expf(A_log[e1 * 16 + g * 4 + 2]);
    float Ae1w = -__expf(A_log[e1 * 16 + g * 4 + 3]);

    // preload t=0
    int gb0 = b * 1216 + (v << 6) + e0;
    float pdt0 = g_dt[gb0], pdt1 = g_dt[gb0 + 32];
    float pg0  = g_G[gb0],  pg1  = g_G[gb0 + 32];
    if (tid < VG) {
        int bcb = (b * VG + tid) * 16 + (g << 2);
        BS4[tid] = *(const float4*)&g_B[bcb];
        CS4[tid] = *(const float4*)&g_C[bcb];
    }
    float* yout = g_yp + (size_t)g * YPG;
    __syncthreads();

    for (int t = 0; t < LS; ++t) {
        // ---- E: S = (R + bA)*exp(dt*A) + G*B ----
        {
            float4 b4 = BS4[v];
            float ba0 = bAs[e0], ba1 = bAs[e1];
            int rb = v << 8;
            float4 s0, s1;
            s0.x = fmaf(Rn[rb +       e0] + ba0, __expf(pdt0 * Ae0x), pg0 * b4.x);
            s0.y = fmaf(Rn[rb +  64 + e0] + ba0, __expf(pdt0 * Ae0y), pg0 * b4.y);
            s0.z = fmaf(Rn[rb + 128 + e0] + ba0, __expf(pdt0 * Ae0z), pg0 * b4.z);
            s0.w = fmaf(Rn[rb + 192 + e0] + ba0, __expf(pdt0 * Ae0w), pg0 * b4.w);
            s1.x = fmaf(Rn[rb +       e1] + ba1, __expf(pdt1 * Ae1x), pg1 * b4.x);
            s1.y = fmaf(Rn[rb +  64 + e1] + ba1, __expf(pdt1 * Ae1y), pg1 * b4.y);
            s1.z = fmaf(Rn[rb + 128 + e1] + ba1, __expf(pdt1 * Ae1z), pg1 * b4.z);
            s1.w = fmaf(Rn[rb + 192 + e1] + ba1, __expf(pdt1 * Ae1w), pg1 * b4.w);
            S4[(v << 6) + e0] = s0; S4[(v << 6) + e1] = s1;
        }
        __syncthreads();

        // ---- Agg: Q = Nm*S ; QC = Q.C ; CSV ----
        {
            float4 qa = {0,0,0,0}, qb = {0,0,0,0};
            #pragma unroll
            for (int vp = 0; vp < VG; ++vp) {
                float nm = NMs[v * VG + vp];
                float4 sa = S4[(vp << 6) + e0], sb = S4[(vp << 6) + e1];
                qa.x = fmaf(nm, sa.x, qa.x); qa.y = fmaf(nm, sa.y, qa.y);
                qa.z = fmaf(nm, sa.z, qa.z); qa.w = fmaf(nm, sa.w, qa.w);
                qb.x = fmaf(nm, sb.x, qb.x); qb.y = fmaf(nm, sb.y, qb.y);
                qb.z = fmaf(nm, sb.z, qb.z); qb.w = fmaf(nm, sb.w, qb.w);
            }
            Q4[(v << 6) + e0] = qa; Q4[(v << 6) + e1] = qb;
            float4 c = CS4[v];
            QCs[(v << 6) + e0] = qa.x*c.x + qa.y*c.y + qa.z*c.z + qa.w*c.w;
            QCs[(v << 6) + e1] = qb.x*c.x + qb.y*c.y + qb.z*c.z + qb.w*c.w;
            if (tid < VG) { float4 cc = CS4[tid]; CSVs[tid] = cc.x + cc.y + cc.z + cc.w; }
        }
        __syncthreads();

        // ---- GEMM: R(t+1)=WA@Q ; y(t)=WC@QC + bC*CSV ; prefetch t+1 ----
        {
            int tn = (t + 1 < LS) ? t + 1 : t;
            int gbase = tn * ROW + b * 1216 + (v << 6) + e0;
            float ndt0 = g_dt[gbase], ndt1 = g_dt[gbase + 32];
            float ng0  = g_G[gbase],  ng1  = g_G[gbase + 32];
            float4 nB, nC;
            if (tid < VG) {
                int bcb = tn * BCR + (b * VG + tid) * 16 + (g << 2);
                nB = *(const float4*)&g_B[bcb];
                nC = *(const float4*)&g_C[bcb];
            }
            if (tid < 304) {
                int vi = tid >> 4, ei = tid & 15;
                float4 a0 = {0,0,0,0}, a1 = a0, a2 = a0, a3 = a0;
                #pragma unroll 4
                for (int d = 0; d < 64; ++d) {
                    float4 q = Q4[(vi << 6) + d];
                    float4 w = WAe4[(d << 4) + ei];
                    a0.x = fmaf(w.x, q.x, a0.x); a0.y = fmaf(w.x, q.y, a0.y);
                    a0.z = fmaf(w.x, q.z, a0.z); a0.w = fmaf(w.x, q.w, a0.w);
                    a1.x = fmaf(w.y, q.x, a1.x); a1.y = fmaf(w.y, q.y, a1.y);
                    a1.z = fmaf(w.y, q.z, a1.z); a1.w = fmaf(w.y, q.w, a1.w);
                    a2.x = fmaf(w.z, q.x, a2.x); a2.y = fmaf(w.z, q.y, a2.y);
                    a2.z = fmaf(w.z, q.z, a2.z); a2.w = fmaf(w.z, q.w, a2.w);
                    a3.x = fmaf(w.w, q.x, a3.x); a3.y = fmaf(w.w, q.y, a3.y);
                    a3.z = fmaf(w.w, q.z, a3.z); a3.w = fmaf(w.w, q.w, a3.w);
                }
                int rb = vi << 6;  // vi*64 float4 units
                Rn4[rb      + ei] = make_float4(a0.x, a1.x, a2.x, a3.x);
                Rn4[rb + 16 + ei] = make_float4(a0.y, a1.y, a2.y, a3.y);
                Rn4[rb + 32 + ei] = make_float4(a0.z, a1.z, a2.z, a3.z);
                Rn4[rb + 48 + ei] = make_float4(a0.w, a1.w, a2.w, a3.w);
            } else {
                int yt = tid - 304, vi = yt >> 4, ei = yt & 15;
                float csv = CSVs[vi];
                float4 bc = bC4[ei];
                float4 acc = make_float4(bc.x*csv, bc.y*csv, bc.z*csv, bc.w*csv);
                #pragma unroll 4
                for (int d = 0; d < 64; ++d) {
                    float qc = QCs[(vi << 6) + d];
                    float4 w = WCe4[(d << 4) + ei];
                    acc.x = fmaf(w.x, qc, acc.x); acc.y = fmaf(w.y, qc, acc.y);
                    acc.z = fmaf(w.z, qc, acc.z); acc.w = fmaf(w.w, qc, acc.w);
                }
                ((float4*)(yout + (size_t)t * ROW + (b * VG + vi) * 64))[ei] = acc;
            }
            if (tid < VG) { BS4[tid] = nB; CS4[tid] = nC; }
            pdt0 = ndt0; pdt1 = ndt1; pg0 = ng0; pg1 = ng1;
        }
        __syncthreads();
    }
}

// ---------- post ----------
__global__ void __launch_bounds__(64) k_post(
    const float* __restrict__ Dp, const float* __restrict__ opw, float* __restrict__ out)
{
    __shared__ float ys[64];
    int pos = blockIdx.x;
    int node = pos >> 8, t = pos & 255;
    int e = threadIdx.x;
    int ib = t * ROW + node * 64 + e;
    float y = g_yp[ib] + g_yp[YPG + ib] + g_yp[2 * YPG + ib] + g_yp[3 * YPG + ib];
    y = fmaf(Dp[e], g_u[ib], y);
    float z = g_z[ib];
    y *= z / (1.f + expf(-z));
    ys[e] = y;
    __syncthreads();
    if (e < 32) {
        float a = 0.f;
        #pragma unroll
        for (int k = 0; k < 64; ++k) a = fmaf(opw[e * 64 + k], ys[k], a);
        out[pos * 32 + e] = a;
    }
}

extern "C" void kernel_launch(void* const* d_in, const int* in_sizes, int n_in,
                              void* d_out, int out_size) {
    const float* x_in = (const float*)d_in[0];
    const int*   ei   = (const int*)  d_in[1];
    const float* ew   = (const float*)d_in[2];
    const float* ipw  = (const float*)d_in[3];
    const float* xpw  = (const float*)d_in[4];
    const float* dtw  = (const float*)d_in[5];
    const float* dtb  = (const float*)d_in[6];
    const float* Alog = (const float*)d_in[7];
    const float* Dp   = (const float*)d_in[8];
    const float* opw  = (const float*)d_in[9];
    const float* gAw  = (const float*)d_in[10];
    const float* gAb  = (const float*)d_in[11];
    const float* gBw  = (const float*)d_in[12];
    const float* gBb  = (const float*)d_in[13];
    const float* gCw  = (const float*)d_in[14];
    const float* gCb  = (const float*)d_in[15];
    float* out = (float*)d_out;
    int E = in_sizes[1] / 2;

    static int smem_set = 0;
    if (!smem_set) {
        cudaFuncSetAttribute(k_scan, cudaFuncAttributeMaxDynamicSharedMemorySize, SMTOT * 4);
        smem_set = 1;
    }

    k_zero<<<48, 256>>>();
    k_deg <<<(E + NN + 255) / 256, 256>>>(ei, ew, E);
    k_nmat<<<(E + NN + 255) / 256, 256>>>(ei, ew, E);
    k_tr  <<<16, 256>>>(gBw);
    k_pre <<<NN * LS, 64>>>(x_in, ipw, xpw, dtw, dtb);
    k_ub  <<<LS * 32, 320>>>(gBb);
    k_scan<<<128, 608, SMTOT * 4>>>(Alog, gAw, gAb, gCw, gCb);
    k_post<<<NN * LS, 64>>>(Dp, opw, out);
}

// round 6
// speedup vs baseline: 2.0001x; 1.7338x over previous
#include <cuda_runtime.h>
#include <math.h>

#define VG  19
#define NN  608
#define LS  256
#define ROW 38912   /* 608*64 */
#define BCR 9728    /* 608*16 */
#define YPG 9961472 /* 256*608*64 */
#define NTH 608

__device__ __align__(16) float g_deg[NN];            // zero-init; re-zeroed by k_post
__device__ __align__(16) float g_Nm[32 * 361];
__device__ __align__(16) float g_dt[LS * NN * 64];
__device__ __align__(16) float g_u [LS * NN * 64];
__device__ __align__(16) float g_z [LS * NN * 64];
__device__ __align__(16) float g_B [LS * NN * 16];
__device__ __align__(16) float g_C [LS * NN * 16];
__device__ __align__(16) float g_G [LS * NN * 64];
__device__ __align__(16) float g_yp[4 * YPG];

__device__ __forceinline__ float softplusf(float x) {
    return x > 20.f ? x : log1pf(expf(x));
}

// ---------- launch 1: degree (atomics; g_deg pre-zeroed) ----------
__global__ void k_deg(const int* __restrict__ ei, const float* __restrict__ ew, int E) {
    int i = blockIdx.x * blockDim.x + threadIdx.x;
    if (i < E)           atomicAdd(&g_deg[ei[E + i]], ew[i]);
    else if (i < E + NN) atomicAdd(&g_deg[i - E], 1.f);
}

// ---------- launch 2: normalized adjacency ----------
__global__ void k_nmat(const int* __restrict__ ei, const float* __restrict__ ew, int E) {
    int i = blockIdx.x * blockDim.x + threadIdx.x;
    if (i < E) {
        int s = ei[i], d = ei[E + i];
        float nm = ew[i] * rsqrtf(fmaxf(g_deg[s], 1e-12f)) * rsqrtf(fmaxf(g_deg[d], 1e-12f));
        int bb = d / VG;
        g_Nm[bb * 361 + (d - bb * VG) * VG + (s - bb * VG)] = nm;
    } else if (i < E + NN) {
        int vv = i - E;
        float r = rsqrtf(fmaxf(g_deg[vv], 1e-12f));
        g_Nm[(vv / VG) * 361 + (vv % VG) * VG + (vv % VG)] = r * r;
    }
}

// ---------- launch 3: fused projections + ub precompute, block per (t,b) ----------
__global__ void __launch_bounds__(NTH) k_preub(
    const float* __restrict__ x_in, const float* __restrict__ ipw,
    const float* __restrict__ xpw,  const float* __restrict__ dtw,
    const float* __restrict__ dtb,  const float* __restrict__ gBw,
    const float* __restrict__ gBb)
{
    __shared__ __align__(16) float wsh[4096];    // ipw^T then gBw^T
    __shared__ __align__(16) float xs[608];
    __shared__ __align__(16) float us[1216];
    __shared__ __align__(16) float uaS[1216];
    __shared__ __align__(16) float xpws[2304];   // [64 d][36 pad j]
    __shared__ __align__(16) float bBs[64];
    __shared__ __align__(16) float dtr[40];
    __shared__ __align__(16) float nm[364];

    int tb = blockIdx.x, t = tb >> 5, b = tb & 31;
    int tid = threadIdx.x;
    int v = tid >> 5, l = tid & 31;

    for (int i = tid; i < 4096; i += NTH) wsh[(i & 31) * 128 + (i >> 5)] = ipw[i];
    { int node = b * VG + v; xs[tid] = x_in[node * 8192 + t * 32 + l]; }
    for (int i = tid; i < 2176; i += NTH) { int j = i >> 6, d = i & 63; xpws[d * 36 + j] = xpw[i]; }
    for (int i = tid; i < 361; i += NTH) nm[i] = g_Nm[b * 361 + i];
    if (tid < 64) bBs[tid] = gBb[tid];
    __syncthreads();

    // u, z
    float u0 = 0, u1 = 0, z0 = 0, z1 = 0;
    #pragma unroll 8
    for (int k = 0; k < 32; ++k) {
        float xk = xs[v * 32 + k];
        u0 = fmaf(wsh[k * 128 + l], xk, u0);
        u1 = fmaf(wsh[k * 128 + 32 + l], xk, u1);
        z0 = fmaf(wsh[k * 128 + 64 + l], xk, z0);
        z1 = fmaf(wsh[k * 128 + 96 + l], xk, z1);
    }
    us[v * 64 + l] = u0; us[v * 64 + 32 + l] = u1;
    int gb = t * ROW + (b * VG + v) * 64;
    g_u[gb + l] = u0; g_u[gb + 32 + l] = u1;
    g_z[gb + l] = z0; g_z[gb + 32 + l] = z1;
    __syncthreads();

    // x_dbl (646 tasks) + reload wsh with gBw^T
    for (int idx = tid; idx < 646; idx += NTH) {
        int vv = idx / 34, j = idx - vv * 34;
        float a = 0.f;
        #pragma unroll 8
        for (int d = 0; d < 64; ++d) a = fmaf(xpws[d * 36 + j], us[vv * 64 + d], a);
        if (j < 2)       dtr[vv * 2 + j] = a;
        else if (j < 18) g_B[t * BCR + (b * VG + vv) * 16 + (j - 2)] = a;
        else             g_C[t * BCR + (b * VG + vv) * 16 + (j - 18)] = a;
    }
    for (int i = tid; i < 4096; i += NTH) wsh[(i & 63) * 64 + (i >> 6)] = gBw[i];
    __syncthreads();

    // dt
    float r0 = dtr[v * 2], r1 = dtr[v * 2 + 1];
    float d0 = softplusf(fmaf(r0, dtw[l * 2], fmaf(r1, dtw[l * 2 + 1], dtb[l])));
    float d1 = softplusf(fmaf(r0, dtw[(l + 32) * 2], fmaf(r1, dtw[(l + 32) * 2 + 1], dtb[l + 32])));
    g_dt[gb + l] = d0; g_dt[gb + 32 + l] = d1;

    // ua = Nm @ u
    float a0 = 0, a1 = 0;
    #pragma unroll
    for (int vp = 0; vp < VG; ++vp) {
        float n = nm[v * VG + vp];
        a0 = fmaf(n, us[vp * 64 + l], a0);
        a1 = fmaf(n, us[vp * 64 + 32 + l], a1);
    }
    uaS[v * 64 + l] = a0; uaS[v * 64 + 32 + l] = a1;
    __syncthreads();

    // G = (gBw @ ua + bB) * dt
    float gg0 = bBs[l], gg1 = bBs[l + 32];
    #pragma unroll 8
    for (int k = 0; k < 64; ++k) {
        float ua0 = uaS[v * 64 + k];
        gg0 = fmaf(wsh[k * 64 + l], ua0, gg0);
        gg1 = fmaf(wsh[k * 64 + 32 + l], ua0, gg1);
    }
    g_G[gb + l] = gg0 * d0; g_G[gb + 32 + l] = gg1 * d1;
}

// ---------- launch 4: scan, persistent, 128 CTAs ----------
#define O_WA  0
#define O_WC  4096
#define O_NM  8192
#define O_S   8560
#define O_Q   13424
#define O_R   18288
#define O_QC  23152
#define O_CSV 24368
#define O_BS  24388
#define O_CS  24464
#define O_BA  24540
#define O_BC  24604
#define SMTOT 24668

__global__ void __launch_bounds__(NTH, 1) k_scan(
    const float* __restrict__ A_log,
    const float* __restrict__ gAw, const float* __restrict__ gAb,
    const float* __restrict__ gCw, const float* __restrict__ gCb)
{
    extern __shared__ __align__(16) float sm[];
    float* WAe = sm + O_WA;   float* WCe = sm + O_WC;
    float* NMs = sm + O_NM;   float* QCs = sm + O_QC;
    float* CSVs = sm + O_CSV; float* bAs = sm + O_BA;
    float4* S4 = (float4*)(sm + O_S);
    float4* Q4 = (float4*)(sm + O_Q);
    float4* R4 = (float4*)(sm + O_R);
    float4* BS4 = (float4*)(sm + O_BS);
    float4* CS4 = (float4*)(sm + O_CS);
    const float4* WCe4 = (const float4*)WCe;
    const float4* bC4  = (const float4*)(sm + O_BC);

    const int tid = threadIdx.x;
    const int b = blockIdx.x >> 2, g = blockIdx.x & 3;
    const int v = tid >> 5, e0 = tid & 31, e1 = e0 + 32;

    for (int i = tid; i < 4096; i += NTH) {
        WAe[i] = gAw[(i & 63) * 64 + (i >> 6)];
        WCe[i] = gCw[(i & 63) * 64 + (i >> 6)];
    }
    for (int i = tid; i < 361; i += NTH) NMs[i] = g_Nm[b * 361 + i];
    for (int i = tid; i < 4864; i += NTH) sm[O_R + i] = 0.f;
    if (tid < 64) { bAs[tid] = gAb[tid]; sm[O_BC + tid] = gCb[tid]; }

    float Ax0 = -__expf(A_log[e0 * 16 + g * 4 + 0]);
    float Ay0 = -__expf(A_log[e0 * 16 + g * 4 + 1]);
    float Az0 = -__expf(A_log[e0 * 16 + g * 4 + 2]);
    float Aw0 = -__expf(A_log[e0 * 16 + g * 4 + 3]);
    float Ax1 = -__expf(A_log[e1 * 16 + g * 4 + 0]);
    float Ay1 = -__expf(A_log[e1 * 16 + g * 4 + 1]);
    float Az1 = -__expf(A_log[e1 * 16 + g * 4 + 2]);
    float Aw1 = -__expf(A_log[e1 * 16 + g * 4 + 3]);

    // preload t=0
    int gb0 = b * 1216 + (v << 6) + e0;
    float pdt0 = g_dt[gb0], pdt1 = g_dt[gb0 + 32];
    float pg0  = g_G[gb0],  pg1  = g_G[gb0 + 32];
    if (tid < VG) {
        int bcb = (b * VG + tid) * 16 + (g << 2);
        BS4[tid] = *(const float4*)&g_B[bcb];
        CS4[tid] = *(const float4*)&g_C[bcb];
    }
    float* yout = g_yp + (size_t)g * YPG;
    __syncthreads();

    for (int t = 0; t < LS; ++t) {
        // ---- E: S = (R + bA)*exp(dt*A) + G*B ----
        {
            float4 b4 = BS4[v];
            float ba0 = bAs[e0], ba1 = bAs[e1];
            float4 r = R4[(v << 6) + e0], s;
            s.x = fmaf(r.x + ba0, __expf(pdt0 * Ax0), pg0 * b4.x);
            s.y = fmaf(r.y + ba0, __expf(pdt0 * Ay0), pg0 * b4.y);
            s.z = fmaf(r.z + ba0, __expf(pdt0 * Az0), pg0 * b4.z);
            s.w = fmaf(r.w + ba0, __expf(pdt0 * Aw0), pg0 * b4.w);
            S4[(v << 6) + e0] = s;
            r = R4[(v << 6) + e1];
            s.x = fmaf(r.x + ba1, __expf(pdt1 * Ax1), pg1 * b4.x);
            s.y = fmaf(r.y + ba1, __expf(pdt1 * Ay1), pg1 * b4.y);
            s.z = fmaf(r.z + ba1, __expf(pdt1 * Az1), pg1 * b4.z);
            s.w = fmaf(r.w + ba1, __expf(pdt1 * Aw1), pg1 * b4.w);
            S4[(v << 6) + e1] = s;
        }
        __syncthreads();

        // ---- Agg: Q = Nm*S ; QC = Q.C ; CSV ----
        {
            float4 qa = {0,0,0,0}, qb = {0,0,0,0};
            #pragma unroll
            for (int vp = 0; vp < VG; ++vp) {
                float nmv = NMs[v * VG + vp];
                float4 sa = S4[(vp << 6) + e0], sb = S4[(vp << 6) + e1];
                qa.x = fmaf(nmv, sa.x, qa.x); qa.y = fmaf(nmv, sa.y, qa.y);
                qa.z = fmaf(nmv, sa.z, qa.z); qa.w = fmaf(nmv, sa.w, qa.w);
                qb.x = fmaf(nmv, sb.x, qb.x); qb.y = fmaf(nmv, sb.y, qb.y);
                qb.z = fmaf(nmv, sb.z, qb.z); qb.w = fmaf(nmv, sb.w, qb.w);
            }
            Q4[(v << 6) + e0] = qa; Q4[(v << 6) + e1] = qb;
            float4 c = CS4[v];
            QCs[(v << 6) + e0] = qa.x*c.x + qa.y*c.y + qa.z*c.z + qa.w*c.w;
            QCs[(v << 6) + e1] = qb.x*c.x + qb.y*c.y + qb.z*c.z + qb.w*c.w;
            if (tid < VG) { float4 cc = CS4[tid]; CSVs[tid] = cc.x + cc.y + cc.z + cc.w; }
        }
        __syncthreads();

        // ---- GEMM (balanced): R(t+1) [1216 tasks] + y(t) [304 tasks] ----
        {
            int tn = (t + 1 < LS) ? t + 1 : t;
            // stage next-step B/C directly into smem (consumed after the barrier)
            if (tid < VG) {
                int bcb = tn * BCR + (b * VG + tid) * 16 + (g << 2);
                BS4[tid] = *(const float4*)&g_B[bcb];
                CS4[tid] = *(const float4*)&g_C[bcb];
            }
            int gbase = tn * ROW + b * 1216 + (v << 6) + e0;
            float ndt0 = g_dt[gbase], ndt1 = g_dt[gbase + 32];
            float ng0  = g_G[gbase],  ng1  = g_G[gbase + 32];

            #pragma unroll 1
            for (int task = tid; task < 1520; task += NTH) {
                if (task < 1216) {
                    int tv = task >> 6, te = task & 63;
                    float4 acc = {0, 0, 0, 0};
                    #pragma unroll 8
                    for (int k = 0; k < 64; ++k) {
                        float w = WAe[(k << 6) + te];
                        float4 q = Q4[(tv << 6) + k];
                        acc.x = fmaf(w, q.x, acc.x); acc.y = fmaf(w, q.y, acc.y);
                        acc.z = fmaf(w, q.z, acc.z); acc.w = fmaf(w, q.w, acc.w);
                    }
                    R4[(tv << 6) + te] = acc;
                } else {
                    int idx = task - 1216;
                    int tv = idx >> 4, eg = idx & 15;
                    float csv = CSVs[tv];
                    float4 bc = bC4[eg];
                    float4 acc = make_float4(bc.x * csv, bc.y * csv, bc.z * csv, bc.w * csv);
                    #pragma unroll 8
                    for (int k = 0; k < 64; ++k) {
                        float qc = QCs[(tv << 6) + k];
                        float4 w = WCe4[(k << 4) + eg];
                        acc.x = fmaf(w.x, qc, acc.x); acc.y = fmaf(w.y, qc, acc.y);
                        acc.z = fmaf(w.z, qc, acc.z); acc.w = fmaf(w.w, qc, acc.w);
                    }
                    *(float4*)(yout + (size_t)t * ROW + (b * VG + tv) * 64 + (eg << 2)) = acc;
                }
            }
            pdt0 = ndt0; pdt1 = ndt1; pg0 = ng0; pg1 = ng1;
        }
        __syncthreads();
    }
}

// ---------- launch 5: post + deg re-zero for next call ----------
__global__ void __launch_bounds__(256) k_post(
    const float* __restrict__ Dp, const float* __restrict__ opw, float* __restrict__ out)
{
    __shared__ float ys[256];
    int tid = threadIdx.x;
    if (blockIdx.x < 3) { int i = blockIdx.x * 256 + tid; if (i < NN) g_deg[i] = 0.f; }
    int sub = tid >> 6, e = tid & 63;
    int pos = blockIdx.x * 4 + sub;
    int node = pos >> 8, t = pos & 255;
    int ib = t * ROW + node * 64 + e;
    float y = g_yp[ib] + g_yp[YPG + ib] + g_yp[2 * YPG + ib] + g_yp[3 * YPG + ib];
    y = fmaf(Dp[e], g_u[ib], y);
    float z = g_z[ib];
    y *= z / (1.f + expf(-z));
    ys[sub * 64 + e] = y;
    __syncthreads();
    if (e < 32) {
        float a = 0.f;
        #pragma unroll 8
        for (int k = 0; k < 64; ++k) a = fmaf(opw[e * 64 + k], ys[sub * 64 + k], a);
        out[pos * 32 + e] = a;
    }
}

extern "C" void kernel_launch(void* const* d_in, const int* in_sizes, int n_in,
                              void* d_out, int out_size) {
    const float* x_in = (const float*)d_in[0];
    const int*   ei   = (const int*)  d_in[1];
    const float* ew   = (const float*)d_in[2];
    const float* ipw  = (const float*)d_in[3];
    const float* xpw  = (const float*)d_in[4];
    const float* dtw  = (const float*)d_in[5];
    const float* dtb  = (const float*)d_in[6];
    const float* Alog = (const float*)d_in[7];
    const float* Dp   = (const float*)d_in[8];
    const float* opw  = (const float*)d_in[9];
    const float* gAw  = (const float*)d_in[10];
    const float* gAb  = (const float*)d_in[11];
    const float* gBw  = (const float*)d_in[12];
    const float* gBb  = (const float*)d_in[13];
    const float* gCw  = (const float*)d_in[14];
    const float* gCb  = (const float*)d_in[15];
    float* out = (float*)d_out;
    int E = in_sizes[1] / 2;

    static int smem_set = 0;
    if (!smem_set) {
        cudaFuncSetAttribute(k_scan, cudaFuncAttributeMaxDynamicSharedMemorySize, SMTOT * 4);
        smem_set = 1;
    }

    k_deg  <<<(E + NN + 255) / 256, 256>>>(ei, ew, E);
    k_nmat <<<(E + NN + 255) / 256, 256>>>(ei, ew, E);
    k_preub<<<LS * 32, NTH>>>(x_in, ipw, xpw, dtw, dtb, gBw, gBb);
    k_scan <<<128, NTH, SMTOT * 4>>>(Alog, gAw, gAb, gCw, gCb);
    k_post <<<NN * LS / 4, 256>>>(Dp, opw, out);
}

// round 8
// speedup vs baseline: 2.3220x; 1.1609x over previous
#include <cuda_runtime.h>
#include <math.h>

#define VG  19
#define NN  608
#define LS  256
#define ROW 38912   /* 608*64 */
#define BCR 9728    /* 608*16 */
#define YPG 9961472 /* 256*608*64 */
#define NTH 608

__device__ __align__(16) float g_deg[NN];            // zero-init; re-zeroed by k_post
__device__ __align__(16) float g_Nm[32 * 361];
__device__ __align__(16) float g_dt[LS * NN * 64];
__device__ __align__(16) float g_u [LS * NN * 64];
__device__ __align__(16) float g_z [LS * NN * 64];
__device__ __align__(16) float g_B [LS * NN * 16];
__device__ __align__(16) float g_C [LS * NN * 16];
__device__ __align__(16) float g_G [LS * NN * 64];
__device__ __align__(16) float g_yp[4 * YPG];

__device__ __forceinline__ float softplusf(float x) {
    return x > 20.f ? x : log1pf(expf(x));
}

// ---------- launch 1: degree ----------
__global__ void k_deg(const int* __restrict__ ei, const float* __restrict__ ew, int E) {
    int i = blockIdx.x * blockDim.x + threadIdx.x;
    if (i < E)           atomicAdd(&g_deg[ei[E + i]], ew[i]);
    else if (i < E + NN) atomicAdd(&g_deg[i - E], 1.f);
}

// ---------- launch 2: normalized adjacency ----------
__global__ void k_nmat(const int* __restrict__ ei, const float* __restrict__ ew, int E) {
    int i = blockIdx.x * blockDim.x + threadIdx.x;
    if (i < E) {
        int s = ei[i], d = ei[E + i];
        float nm = ew[i] * rsqrtf(fmaxf(g_deg[s], 1e-12f)) * rsqrtf(fmaxf(g_deg[d], 1e-12f));
        int bb = d / VG;
        g_Nm[bb * 361 + (d - bb * VG) * VG + (s - bb * VG)] = nm;
    } else if (i < E + NN) {
        int vv = i - E;
        float r = rsqrtf(fmaxf(g_deg[vv], 1e-12f));
        g_Nm[(vv / VG) * 361 + (vv % VG) * VG + (vv % VG)] = r * r;
    }
}

// ---------- launch 3: fused projections + ub precompute, block per (t,b) ----------
__global__ void __launch_bounds__(NTH) k_preub(
    const float* __restrict__ x_in, const float* __restrict__ ipw,
    const float* __restrict__ xpw,  const float* __restrict__ dtw,
    const float* __restrict__ dtb,  const float* __restrict__ gBw,
    const float* __restrict__ gBb)
{
    __shared__ __align__(16) float wsh[4096];    // ipw^T then gBw^T
    __shared__ __align__(16) float xs[608];
    __shared__ __align__(16) float us[1216];
    __shared__ __align__(16) float uaS[1216];
    __shared__ __align__(16) float xpws[2304];   // [64 d][36 pad j]
    __shared__ __align__(16) float bBs[64];
    __shared__ __align__(16) float dtr[40];
    __shared__ __align__(16) float nm[364];

    int tb = blockIdx.x, t = tb >> 5, b = tb & 31;
    int tid = threadIdx.x;
    int v = tid >> 5, l = tid & 31;

    for (int i = tid; i < 4096; i += NTH) wsh[(i & 31) * 128 + (i >> 5)] = ipw[i];
    { int node = b * VG + v; xs[tid] = x_in[node * 8192 + t * 32 + l]; }
    for (int i = tid; i < 2176; i += NTH) { int j = i >> 6, d = i & 63; xpws[d * 36 + j] = xpw[i]; }
    for (int i = tid; i < 361; i += NTH) nm[i] = g_Nm[b * 361 + i];
    if (tid < 64) bBs[tid] = gBb[tid];
    __syncthreads();

    float u0 = 0, u1 = 0, z0 = 0, z1 = 0;
    #pragma unroll 8
    for (int k = 0; k < 32; ++k) {
        float xk = xs[v * 32 + k];
        u0 = fmaf(wsh[k * 128 + l], xk, u0);
        u1 = fmaf(wsh[k * 128 + 32 + l], xk, u1);
        z0 = fmaf(wsh[k * 128 + 64 + l], xk, z0);
        z1 = fmaf(wsh[k * 128 + 96 + l], xk, z1);
    }
    us[v * 64 + l] = u0; us[v * 64 + 32 + l] = u1;
    int gb = t * ROW + (b * VG + v) * 64;
    g_u[gb + l] = u0; g_u[gb + 32 + l] = u1;
    g_z[gb + l] = z0; g_z[gb + 32 + l] = z1;
    __syncthreads();

    for (int idx = tid; idx < 646; idx += NTH) {
        int vv = idx / 34, j = idx - vv * 34;
        float a = 0.f;
        #pragma unroll 8
        for (int d = 0; d < 64; ++d) a = fmaf(xpws[d * 36 + j], us[vv * 64 + d], a);
        if (j < 2)       dtr[vv * 2 + j] = a;
        else if (j < 18) g_B[t * BCR + (b * VG + vv) * 16 + (j - 2)] = a;
        else             g_C[t * BCR + (b * VG + vv) * 16 + (j - 18)] = a;
    }
    for (int i = tid; i < 4096; i += NTH) wsh[(i & 63) * 64 + (i >> 6)] = gBw[i];
    __syncthreads();

    float r0 = dtr[v * 2], r1 = dtr[v * 2 + 1];
    float d0 = softplusf(fmaf(r0, dtw[l * 2], fmaf(r1, dtw[l * 2 + 1], dtb[l])));
    float d1 = softplusf(fmaf(r0, dtw[(l + 32) * 2], fmaf(r1, dtw[(l + 32) * 2 + 1], dtb[l + 32])));
    g_dt[gb + l] = d0; g_dt[gb + 32 + l] = d1;

    float a0 = 0, a1 = 0;
    #pragma unroll
    for (int vp = 0; vp < VG; ++vp) {
        float n = nm[v * VG + vp];
        a0 = fmaf(n, us[vp * 64 + l], a0);
        a1 = fmaf(n, us[vp * 64 + 32 + l], a1);
    }
    uaS[v * 64 + l] = a0; uaS[v * 64 + 32 + l] = a1;
    __syncthreads();

    float gg0 = bBs[l], gg1 = bBs[l + 32];
    #pragma unroll 8
    for (int k = 0; k < 64; ++k) {
        float ua0 = uaS[v * 64 + k];
        gg0 = fmaf(wsh[k * 64 + l], ua0, gg0);
        gg1 = fmaf(wsh[k * 64 + 32 + l], ua0, gg1);
    }
    g_G[gb + l] = gg0 * d0; g_G[gb + 32 + l] = gg1 * d1;
}

// ---------- launch 4: scan, persistent, 128 CTAs ----------
#define O_WA  0
#define O_WC  4096
#define O_NM  8192
#define O_S   8576
#define O_Q   13440
#define O_R   18304
#define O_QC  23168
#define O_CSV 24384
#define O_BS  24404
#define O_CS  24480
#define O_BA  24556
#define O_BC  24620
#define SMTOT 24684

__global__ void __launch_bounds__(NTH, 1) k_scan(
    const float* __restrict__ A_log,
    const float* __restrict__ gAw, const float* __restrict__ gAb,
    const float* __restrict__ gCw, const float* __restrict__ gCb)
{
    extern __shared__ __align__(16) float sm[];
    float* WAe = sm + O_WA;   float* WCe = sm + O_WC;
    float* NMs = sm + O_NM;   float* QCs = sm + O_QC;
    float* CSVs = sm + O_CSV; float* bAs = sm + O_BA;
    float4* S4 = (float4*)(sm + O_S);
    float4* Q4 = (float4*)(sm + O_Q);
    float4* R4 = (float4*)(sm + O_R);
    float4* BS4 = (float4*)(sm + O_BS);
    float4* CS4 = (float4*)(sm + O_CS);
    const float4* WAe4 = (const float4*)WAe;
    const float4* WCe4 = (const float4*)WCe;
    const float4* bC4  = (const float4*)(sm + O_BC);

    const int tid = threadIdx.x;
    const int b = blockIdx.x >> 2, g = blockIdx.x & 3;
    const int v = tid >> 5, e0 = tid & 31, e1 = e0 + 32;   // E-phase mapping
    const int ae = tid & 63, agrp = tid >> 6;              // Agg mapping (agrp 0..9)
    const int av0 = agrp * 2, av1 = av0 + 1;               // agrp==9 -> v=18 (2 e-slots)

    for (int i = tid; i < 4096; i += NTH) {
        WAe[i] = gAw[(i & 63) * 64 + (i >> 6)];   // WAe[k*64+e] = gAw[e][k]
        WCe[i] = gCw[(i & 63) * 64 + (i >> 6)];
    }
    for (int i = tid; i < 361; i += NTH) NMs[i] = g_Nm[b * 361 + i];
    for (int i = tid; i < 4864; i += NTH) sm[O_R + i] = 0.f;
    if (tid < 64) { bAs[tid] = gAb[tid]; sm[O_BC + tid] = gCb[tid]; }

    float Ax0 = -__expf(A_log[e0 * 16 + g * 4 + 0]);
    float Ay0 = -__expf(A_log[e0 * 16 + g * 4 + 1]);
    float Az0 = -__expf(A_log[e0 * 16 + g * 4 + 2]);
    float Aw0 = -__expf(A_log[e0 * 16 + g * 4 + 3]);
    float Ax1 = -__expf(A_log[e1 * 16 + g * 4 + 0]);
    float Ay1 = -__expf(A_log[e1 * 16 + g * 4 + 1]);
    float Az1 = -__expf(A_log[e1 * 16 + g * 4 + 2]);
    float Aw1 = -__expf(A_log[e1 * 16 + g * 4 + 3]);

    int gb0 = b * 1216 + (v << 6) + e0;
    float pdt0 = g_dt[gb0], pdt1 = g_dt[gb0 + 32];
    float pg0  = g_G[gb0],  pg1  = g_G[gb0 + 32];
    if (tid < VG) {
        int bcb = (b * VG + tid) * 16 + (g << 2);
        BS4[tid] = *(const float4*)&g_B[bcb];
        CS4[tid] = *(const float4*)&g_C[bcb];
    }
    float* yout = g_yp + (size_t)g * YPG;
    __syncthreads();

    for (int t = 0; t < LS; ++t) {
        // ---- E: S = (R + bA)*exp(dt*A) + G*B ----
        {
            float4 b4 = BS4[v];
            float ba0 = bAs[e0], ba1 = bAs[e1];
            float4 r = R4[(v << 6) + e0], s;
            s.x = fmaf(r.x + ba0, __expf(pdt0 * Ax0), pg0 * b4.x);
            s.y = fmaf(r.y + ba0, __expf(pdt0 * Ay0), pg0 * b4.y);
            s.z = fmaf(r.z + ba0, __expf(pdt0 * Az0), pg0 * b4.z);
            s.w = fmaf(r.w + ba0, __expf(pdt0 * Aw0), pg0 * b4.w);
            S4[(v << 6) + e0] = s;
            r = R4[(v << 6) + e1];
            s.x = fmaf(r.x + ba1, __expf(pdt1 * Ax1), pg1 * b4.x);
            s.y = fmaf(r.y + ba1, __expf(pdt1 * Ay1), pg1 * b4.y);
            s.z = fmaf(r.z + ba1, __expf(pdt1 * Az1), pg1 * b4.z);
            s.w = fmaf(r.w + ba1, __expf(pdt1 * Aw1), pg1 * b4.w);
            S4[(v << 6) + e1] = s;
        }
        __syncthreads();

        // ---- Agg (v-paired): Q = Nm*S ; QC = Q.C ; CSV ----
        {
            if (agrp < 9) {
                float4 q0 = {0,0,0,0}, q1 = {0,0,0,0};
                const float* nrow0 = NMs + av0 * VG;
                const float* nrow1 = NMs + av1 * VG;
                #pragma unroll
                for (int vp = 0; vp < VG; ++vp) {
                    float4 s4 = S4[(vp << 6) + ae];
                    float n0 = nrow0[vp], n1 = nrow1[vp];
                    q0.x = fmaf(n0, s4.x, q0.x); q0.y = fmaf(n0, s4.y, q0.y);
                    q0.z = fmaf(n0, s4.z, q0.z); q0.w = fmaf(n0, s4.w, q0.w);
                    q1.x = fmaf(n1, s4.x, q1.x); q1.y = fmaf(n1, s4.y, q1.y);
                    q1.z = fmaf(n1, s4.z, q1.z); q1.w = fmaf(n1, s4.w, q1.w);
                }
                Q4[(av0 << 6) + ae] = q0;
                Q4[(av1 << 6) + ae] = q1;
                float4 c0 = CS4[av0], c1 = CS4[av1];
                QCs[(av0 << 6) + ae] = q0.x*c0.x + q0.y*c0.y + q0.z*c0.z + q0.w*c0.w;
                QCs[(av1 << 6) + ae] = q1.x*c1.x + q1.y*c1.y + q1.z*c1.z + q1.w*c1.w;
            } else {
                // v=18: only 32 threads in this group -> each covers 2 e-slots
                const float* nrow0 = NMs + 18 * VG;
                float4 c0 = CS4[18];
                #pragma unroll
                for (int h = 0; h < 2; ++h) {
                    int aeh = ae + h * 32;   // ae in 0..31 here
                    float4 q0 = {0,0,0,0};
                    #pragma unroll
                    for (int vp = 0; vp < VG; ++vp) {
                        float4 s4 = S4[(vp << 6) + aeh];
                        float n0 = nrow0[vp];
                        q0.x = fmaf(n0, s4.x, q0.x); q0.y = fmaf(n0, s4.y, q0.y);
                        q0.z = fmaf(n0, s4.z, q0.z); q0.w = fmaf(n0, s4.w, q0.w);
                    }
                    Q4[(18 << 6) + aeh] = q0;
                    QCs[(18 << 6) + aeh] = q0.x*c0.x + q0.y*c0.y + q0.z*c0.z + q0.w*c0.w;
                }
            }
            if (tid < VG) { float4 cc = CS4[tid]; CSVs[tid] = cc.x + cc.y + cc.z + cc.w; }
        }
        __syncthreads();

        // ---- GEMM (one balanced round): R(t+1)=WA@Q (304 thr, 4e x 4n tiles)
        //      plus y(t)=WC@QC + bC*CSV (304 thr, 4e tiles); prefetch t+1 ----
        {
            int tn = (t + 1 < LS) ? t + 1 : t;
            if (tid < VG) {
                int bcb = tn * BCR + (b * VG + tid) * 16 + (g << 2);
                BS4[tid] = *(const float4*)&g_B[bcb];
                CS4[tid] = *(const float4*)&g_C[bcb];
            }
            int gbase = tn * ROW + b * 1216 + (v << 6) + e0;
            float ndt0 = g_dt[gbase], ndt1 = g_dt[gbase + 32];
            float ng0  = g_G[gbase],  ng1  = g_G[gbase + 32];

            if (tid < 304) {
                int tv = tid >> 4, eq = tid & 15;
                float4 a0 = {0,0,0,0}, a1 = a0, a2 = a0, a3 = a0;
                #pragma unroll 8
                for (int k = 0; k < 64; ++k) {
                    float4 w = WAe4[(k << 4) + eq];
                    float4 q = Q4[(tv << 6) + k];
                    a0.x = fmaf(w.x, q.x, a0.x); a0.y = fmaf(w.x, q.y, a0.y);
                    a0.z = fmaf(w.x, q.z, a0.z); a0.w = fmaf(w.x, q.w, a0.w);
                    a1.x = fmaf(w.y, q.x, a1.x); a1.y = fmaf(w.y, q.y, a1.y);
                    a1.z = fmaf(w.y, q.z, a1.z); a1.w = fmaf(w.y, q.w, a1.w);
                    a2.x = fmaf(w.z, q.x, a2.x); a2.y = fmaf(w.z, q.y, a2.y);
                    a2.z = fmaf(w.z, q.z, a2.z); a2.w = fmaf(w.z, q.w, a2.w);
                    a3.x = fmaf(w.w, q.x, a3.x); a3.y = fmaf(w.w, q.y, a3.y);
                    a3.z = fmaf(w.w, q.z, a3.z); a3.w = fmaf(w.w, q.w, a3.w);
                }
                int rb = (tv << 6) + (eq << 2);
                R4[rb]     = a0;
                R4[rb + 1] = a1;
                R4[rb + 2] = a2;
                R4[rb + 3] = a3;
            } else {
                int yt = tid - 304;
                int tv = yt >> 4, eq = yt & 15;
                float csv = CSVs[tv];
                float4 bc = bC4[eq];
                float4 acc = make_float4(bc.x * csv, bc.y * csv, bc.z * csv, bc.w * csv);
                #pragma unroll 8
                for (int k = 0; k < 64; ++k) {
                    float qc = QCs[(tv << 6) + k];
                    float4 w = WCe4[(k << 4) + eq];
                    acc.x = fmaf(w.x, qc, acc.x); acc.y = fmaf(w.y, qc, acc.y);
                    acc.z = fmaf(w.z, qc, acc.z); acc.w = fmaf(w.w, qc, acc.w);
                }
                *(float4*)(yout + (size_t)t * ROW + (b * VG + tv) * 64 + (eq << 2)) = acc;
            }
            pdt0 = ndt0; pdt1 = ndt1; pg0 = ng0; pg1 = ng1;
        }
        __syncthreads();
    }
}

// ---------- launch 5: post + deg re-zero ----------
__global__ void __launch_bounds__(256) k_post(
    const float* __restrict__ Dp, const float* __restrict__ opw, float* __restrict__ out)
{
    __shared__ float ys[256];
    int tid = threadIdx.x;
    if (blockIdx.x < 3) { int i = blockIdx.x * 256 + tid; if (i < NN) g_deg[i] = 0.f; }
    int sub = tid >> 6, e = tid & 63;
    int pos = blockIdx.x * 4 + sub;
    int node = pos >> 8, t = pos & 255;
    int ib = t * ROW + node * 64 + e;
    float y = g_yp[ib] + g_yp[YPG + ib] + g_yp[2 * YPG + ib] + g_yp[3 * YPG + ib];
    y = fmaf(Dp[e], g_u[ib], y);
    float z = g_z[ib];
    y *= z / (1.f + expf(-z));
    ys[sub * 64 + e] = y;
    __syncthreads();
    if (e < 32) {
        float a = 0.f;
        #pragma unroll 8
        for (int k = 0; k < 64; ++k) a = fmaf(opw[e * 64 + k], ys[sub * 64 + k], a);
        out[pos * 32 + e] = a;
    }
}

extern "C" void kernel_launch(void* const* d_in, const int* in_sizes, int n_in,
                              void* d_out, int out_size) {
    const float* x_in = (const float*)d_in[0];
    const int*   ei   = (const int*)  d_in[1];
    const float* ew   = (const float*)d_in[2];
    const float* ipw  = (const float*)d_in[3];
    const float* xpw  = (const float*)d_in[4];
    const float* dtw  = (const float*)d_in[5];
    const float* dtb  = (const float*)d_in[6];
    const float* Alog = (const float*)d_in[7];
    const float* Dp   = (const float*)d_in[8];
    const float* opw  = (const float*)d_in[9];
    const float* gAw  = (const float*)d_in[10];
    const float* gAb  = (const float*)d_in[11];
    const float* gBw  = (const float*)d_in[12];
    const float* gBb  = (const float*)d_in[13];
    const float* gCw  = (const float*)d_in[14];
    const float* gCb  = (const float*)d_in[15];
    float* out = (float*)d_out;
    int E = in_sizes[1] / 2;

    static int smem_set = 0;
    if (!smem_set) {
        cudaFuncSetAttribute(k_scan, cudaFuncAttributeMaxDynamicSharedMemorySize, SMTOT * 4);
        smem_set = 1;
    }

    k_deg  <<<(E + NN + 255) / 256, 256>>>(ei, ew, E);
    k_nmat <<<(E + NN + 255) / 256, 256>>>(ei, ew, E);
    k_preub<<<LS * 32, NTH>>>(x_in, ipw, xpw, dtw, dtb, gBw, gBb);
    k_scan <<<128, NTH, SMTOT * 4>>>(Alog, gAw, gAb, gCw, gCb);
    k_post <<<NN * LS / 4, 256>>>(Dp, opw, out);
}